// round 4
// baseline (speedup 1.0000x reference)
#include <cuda_runtime.h>
#include <cstdint>

// snn_input: integrate-and-fire over T=32 steps, N=4194304 neurons.
//   per step: m += image[t]; spk = m >= 1.0f; m -= 1.0f if spk
// Output: [spikes (T*N, 0/1 float32), final mempot (N float32)].
// HBM-bound (1.056 GB irreducible traffic).
// R3: 32B per thread (2 consecutive float4) -> 1KB contiguous per warp per
// stream burst; 4-timestep x 2-lane load batches (MLP=8) to coarsen DRAM
// read/write bursts and improve row locality.

static constexpr int TSTEPS = 32;
static constexpr int TBATCH = 4;
static constexpr float THRES = 1.0f;

__device__ __forceinline__ void if_step(float4& m, const float4 im, float4& s)
{
    m.x += im.x; m.y += im.y; m.z += im.z; m.w += im.w;
    s.x = (m.x >= THRES) ? 1.0f : 0.0f;
    s.y = (m.y >= THRES) ? 1.0f : 0.0f;
    s.z = (m.z >= THRES) ? 1.0f : 0.0f;
    s.w = (m.w >= THRES) ? 1.0f : 0.0f;
    // thres == 1.0 so subtracting s == subtracting s*THRES
    m.x -= s.x; m.y -= s.y; m.z -= s.z; m.w -= s.w;
}

__global__ __launch_bounds__(256) void snn_if_kernel(
    const float4* __restrict__ image,    // [T, N/4] as float4
    const float4* __restrict__ mempot0,  // [N/4]
    float4* __restrict__ out,            // [T*N/4 spikes][N/4 mempot]
    int n4)
{
    // each thread owns 2 consecutive float4 lanes = 32 bytes
    int i = (blockIdx.x * blockDim.x + threadIdx.x) * 2;
    if (i >= n4) return;

    float4 m0 = __ldcs(&mempot0[i]);
    float4 m1 = __ldcs(&mempot0[i + 1]);

#pragma unroll
    for (int tb = 0; tb < TSTEPS / TBATCH; tb++) {
        float4 im[TBATCH][2];
        // front-batched loads: 8 independent LDG.E.128.CS in flight
#pragma unroll
        for (int j = 0; j < TBATCH; j++) {
            size_t base = (size_t)(tb * TBATCH + j) * n4 + i;
            im[j][0] = __ldcs(&image[base]);
            im[j][1] = __ldcs(&image[base + 1]);
        }
        // compute + store burst
#pragma unroll
        for (int j = 0; j < TBATCH; j++) {
            float4 s0, s1;
            if_step(m0, im[j][0], s0);
            if_step(m1, im[j][1], s1);
            size_t base = (size_t)(tb * TBATCH + j) * n4 + i;
            __stcs(&out[base],     s0);
            __stcs(&out[base + 1], s1);
        }
    }
    size_t base = (size_t)TSTEPS * n4 + i;
    __stcs(&out[base],     m0);
    __stcs(&out[base + 1], m1);
}

extern "C" void kernel_launch(void* const* d_in, const int* in_sizes, int n_in,
                              void* d_out, int out_size)
{
    const float4* image   = (const float4*)d_in[0];
    const float4* mempot0 = (const float4*)d_in[1];
    float4*       out     = (float4*)d_out;

    int n  = in_sizes[1];      // 4194304 neurons
    int n4 = n / 4;            // 1048576 float4 lanes
    int nthreads_total = n4 / 2;

    const int threads = 256;
    const int blocks  = (nthreads_total + threads - 1) / threads;
    snn_if_kernel<<<blocks, threads>>>(image, mempot0, out, n4);
}

// round 6
// speedup vs baseline: 1.5377x; 1.5377x over previous
#include <cuda_runtime.h>
#include <cstdint>

// snn_input: integrate-and-fire over T=32 steps, N=4194304 neurons.
//   per step: m += image[t]; spk = m >= 1.0f; m -= 1.0f if spk
// Output: [spikes (T*N, 0/1 float32), final mempot (N float32)].
// HBM-bound (1.056 GB irreducible traffic).
// R5: back to R2's fully-coalesced 1-float4-per-thread layout (R3's
// thread-consecutive pairs broke coalescing: L1 76%, DRAM 53%).
// TBATCH=16 front-batched loads: MLP=16/thread, and halves the
// read-burst/write-burst alternation frequency at the DRAM scheduler.

static constexpr int TSTEPS = 32;
static constexpr int TBATCH = 16;
static constexpr float THRES = 1.0f;

__global__ __launch_bounds__(256) void snn_if_kernel(
    const float4* __restrict__ image,    // [T, N/4] as float4
    const float4* __restrict__ mempot0,  // [N/4]
    float4* __restrict__ out,            // [T*N/4 spikes][N/4 mempot]
    int n4)
{
    int i = blockIdx.x * blockDim.x + threadIdx.x;
    if (i >= n4) return;

    float4 m = __ldcs(&mempot0[i]);

#pragma unroll
    for (int tb = 0; tb < TSTEPS / TBATCH; tb++) {
        float4 im[TBATCH];
        // front-batched loads: 16 independent LDG.E.128.CS in flight
#pragma unroll
        for (int j = 0; j < TBATCH; j++) {
            im[j] = __ldcs(&image[(size_t)(tb * TBATCH + j) * n4 + i]);
        }
        // compute + store burst
#pragma unroll
        for (int j = 0; j < TBATCH; j++) {
            m.x += im[j].x; m.y += im[j].y; m.z += im[j].z; m.w += im[j].w;
            float4 s;
            s.x = (m.x >= THRES) ? 1.0f : 0.0f;
            s.y = (m.y >= THRES) ? 1.0f : 0.0f;
            s.z = (m.z >= THRES) ? 1.0f : 0.0f;
            s.w = (m.w >= THRES) ? 1.0f : 0.0f;
            // thres == 1.0 so subtracting s == subtracting s*THRES
            m.x -= s.x; m.y -= s.y; m.z -= s.z; m.w -= s.w;
            __stcs(&out[(size_t)(tb * TBATCH + j) * n4 + i], s);
        }
    }
    __stcs(&out[(size_t)TSTEPS * n4 + i], m);
}

extern "C" void kernel_launch(void* const* d_in, const int* in_sizes, int n_in,
                              void* d_out, int out_size)
{
    const float4* image   = (const float4*)d_in[0];
    const float4* mempot0 = (const float4*)d_in[1];
    float4*       out     = (float4*)d_out;

    int n  = in_sizes[1];      // 4194304 neurons
    int n4 = n / 4;            // 1048576 float4 lanes

    const int threads = 256;
    const int blocks  = (n4 + threads - 1) / threads;
    snn_if_kernel<<<blocks, threads>>>(image, mempot0, out, n4);
}